// round 1
// baseline (speedup 1.0000x reference)
#include <cuda_runtime.h>
#include <cstdint>

#define EMBED     1024
#define STEPS     8
#define NF        16     // 2*STEPS features
#define NFP       8      // f32x2 feature pairs
#define TOK_TILE  64     // tokens per CTA
#define NTHREADS  256    // 256 threads * 4 dims = 1024 embed dims
#define DPT       4      // embed dims per thread

__device__ __forceinline__ unsigned long long pack2(float a, float b) {
    unsigned long long r;
    asm("mov.b64 %0, {%1, %2};" : "=l"(r) : "f"(a), "f"(b));
    return r;
}

__global__ void __launch_bounds__(NTHREADS, 2)
fractal_embed_kernel(const int*   __restrict__ token_ids,
                     const float* __restrict__ c_table,
                     const float* __restrict__ W,
                     const float* __restrict__ scale_p,
                     float*       __restrict__ out,
                     int n_tokens)
{
    __shared__ __align__(16) float feats_s[TOK_TILE][NF];

    const int tid      = threadIdx.x;
    const int tok_base = blockIdx.x * TOK_TILE;
    if (tok_base >= n_tokens) return;
    const float scale  = *scale_p;

    // ---- Phase A: Julia features for this CTA's token tile ----
    if (tid < TOK_TILE && tok_base + tid < n_tokens) {
        const int   tok = token_ids[tok_base + tid];
        const float cr  = c_table[2 * tok];
        const float ci  = c_table[2 * tok + 1];
        float zr = 0.f, zi = 0.f;
        #pragma unroll
        for (int s = 0; s < STEPS; ++s) {
            const float nzr = zr * zr - zi * zi + cr;
            const float nzi = 2.f * zr * zi + ci;
            zr = nzr; zi = nzi;
            feats_s[tid][2 * s]     = zr;
            feats_s[tid][2 * s + 1] = zi;
        }
    }

    // ---- Per-thread W slice (4 rows x 16 feats), scale folded, f32x2-packed ----
    const int d0 = tid * DPT;
    unsigned long long wreg[DPT][NFP];
    {
        const float2* wp = reinterpret_cast<const float2*>(W + (size_t)d0 * NF);
        #pragma unroll
        for (int j = 0; j < DPT; ++j) {
            #pragma unroll
            for (int p = 0; p < NFP; ++p) {
                float2 w = wp[j * NFP + p];
                wreg[j][p] = pack2(w.x * scale, w.y * scale);
            }
        }
    }
    __syncthreads();

    // ---- Phase B: GEMM-like sweep over tokens ----
    const int tmax = (n_tokens - tok_base < TOK_TILE) ? (n_tokens - tok_base) : TOK_TILE;
    for (int t = 0; t < tmax; ++t) {
        // feats for token t: 16 floats = 4x LDS.128, warp-uniform address (broadcast)
        const ulonglong2* fp = reinterpret_cast<const ulonglong2*>(feats_s[t]);
        ulonglong2 qa = fp[0], qb = fp[1], qc = fp[2], qd = fp[3];
        unsigned long long f2[NFP] = {qa.x, qa.y, qb.x, qb.y, qc.x, qc.y, qd.x, qd.y};

        float res[DPT];
        #pragma unroll
        for (int j = 0; j < DPT; ++j) {
            unsigned long long acc = 0ull;  // (+0.f, +0.f)
            #pragma unroll
            for (int p = 0; p < NFP; ++p)
                asm("fma.rn.f32x2 %0, %1, %2, %0;"
                    : "+l"(acc) : "l"(f2[p]), "l"(wreg[j][p]));
            float lo, hi;
            asm("mov.b64 {%0, %1}, %2;" : "=f"(lo), "=f"(hi) : "l"(acc));
            res[j] = lo + hi;
        }

        float4 o = make_float4(res[0], res[1], res[2], res[3]);
        float4* dst = reinterpret_cast<float4*>(out + (size_t)(tok_base + t) * EMBED) + tid;
        __stcs(dst, o);  // streaming store: write-once output, skip L2 retention
    }
}

extern "C" void kernel_launch(void* const* d_in, const int* in_sizes, int n_in,
                              void* d_out, int out_size)
{
    const int*   token_ids = (const int*)  d_in[0];
    const float* c_table   = (const float*)d_in[1];
    const float* W         = (const float*)d_in[2];
    const float* scale_p   = (const float*)d_in[3];
    float*       out       = (float*)d_out;

    const int n_tokens = in_sizes[0];
    const int blocks   = (n_tokens + TOK_TILE - 1) / TOK_TILE;
    fractal_embed_kernel<<<blocks, NTHREADS>>>(token_ids, c_table, W, scale_p, out, n_tokens);
}